// round 5
// baseline (speedup 1.0000x reference)
#include <cuda_runtime.h>
#include <math.h>

// ---------------------------------------------------------------------------
// Problem constants
// ---------------------------------------------------------------------------
#define NROWS 2048
#define D_R   20000
#define D_M   2000
#define KPROTO 64
#define DIMX  60
#define INV_T 5.0f   // 1/0.2

// scratch layout (floats)
#define O_Q1   0          // 2048*200
#define O_K1   409600     // 2048*200
#define O_Q2   819200     // 2048*50
#define O_K2   921600
#define O_Q    1024000
#define O_K    1126400
#define O_H1   1228800
#define O_H2   1331200    // 2048*200
#define O_HK1  1740800
#define O_HK2  1843200    // 2048*200
#define O_TQ   2252800
#define O_TK   2355200
#define O_X    2457600    // 2048*60
#define SCRATCH_FLOATS 2580480

static __device__ float g_scratch[SCRATCH_FLOATS];

// ---------------------------------------------------------------------------
// Generic tiled SGEMM: C[M,N] = act(A[M,K] @ B[K,N] + bias[N])
// act: 0 = none, 1 = relu, 2 = sigmoid
// Block 64x64, BK=16, 256 threads, 4x4 micro-tile per thread.
// ---------------------------------------------------------------------------
#define BM 64
#define BN 64
#define BK 16
#define TM 4
#define TN 4

__global__ void sgemm_kernel(const float* __restrict__ A,
                             const float* __restrict__ B,
                             const float* __restrict__ bias,
                             float* __restrict__ C,
                             int M, int N, int K, int act)
{
    __shared__ float As[BK][BM];
    __shared__ float Bs[BK][BN];

    const int tid  = threadIdx.x;
    const int row0 = blockIdx.y * BM;
    const int col0 = blockIdx.x * BN;
    const int tx = tid & 15;
    const int ty = tid >> 4;

    float acc[TM][TN];
#pragma unroll
    for (int i = 0; i < TM; i++)
#pragma unroll
        for (int j = 0; j < TN; j++) acc[i][j] = 0.0f;

    for (int k0 = 0; k0 < K; k0 += BK) {
        // load A tile (64 x 16), transposed into As[k][m]
#pragma unroll
        for (int l = 0; l < 4; l++) {
            int e  = tid + l * 256;
            int m  = e / BK;
            int kk = e % BK;
            int gr = row0 + m;
            int gk = k0 + kk;
            As[kk][m] = (gr < M && gk < K) ? A[(size_t)gr * K + gk] : 0.0f;
        }
        // load B tile (16 x 64)
#pragma unroll
        for (int l = 0; l < 4; l++) {
            int e  = tid + l * 256;
            int kk = e / BN;
            int n  = e % BN;
            int gk = k0 + kk;
            int gc = col0 + n;
            Bs[kk][n] = (gk < K && gc < N) ? B[(size_t)gk * N + gc] : 0.0f;
        }
        __syncthreads();

#pragma unroll
        for (int kk = 0; kk < BK; kk++) {
            float a[TM], b[TN];
#pragma unroll
            for (int i = 0; i < TM; i++) a[i] = As[kk][ty * TM + i];
#pragma unroll
            for (int j = 0; j < TN; j++) b[j] = Bs[kk][tx * TN + j];
#pragma unroll
            for (int i = 0; i < TM; i++)
#pragma unroll
                for (int j = 0; j < TN; j++)
                    acc[i][j] += a[i] * b[j];
        }
        __syncthreads();
    }

#pragma unroll
    for (int i = 0; i < TM; i++) {
        int r = row0 + ty * TM + i;
        if (r >= M) continue;
#pragma unroll
        for (int j = 0; j < TN; j++) {
            int c = col0 + tx * TN + j;
            if (c >= N) continue;
            float v = acc[i][j] + bias[c];
            if (act == 1)      v = fmaxf(v, 0.0f);
            else if (act == 2) v = 1.0f / (1.0f + expf(-v));
            C[(size_t)r * N + c] = v;
        }
    }
}

// ---------------------------------------------------------------------------
// Per-row fusion: s = q+k, s_n = s/max(||s||,1e-12),
// t[d] = sum_g tq[g*10+d]*tk[g*10+d], fbn = sqrt(relu(t))-sqrt(relu(-t))
// X = [s_n (50) | fbn (10)]
// ---------------------------------------------------------------------------
__global__ void fuse_X_kernel(const float* __restrict__ q,
                              const float* __restrict__ k,
                              const float* __restrict__ tq,
                              const float* __restrict__ tk,
                              float* __restrict__ X)
{
    int row = blockIdx.x * blockDim.x + threadIdx.x;
    if (row >= NROWS) return;

    const float* qr  = q  + row * 50;
    const float* kr  = k  + row * 50;
    const float* tqr = tq + row * 50;
    const float* tkr = tk + row * 50;
    float* xr = X + row * 60;

    float s[50];
    float ss = 0.0f;
#pragma unroll
    for (int i = 0; i < 50; i++) {
        s[i] = qr[i] + kr[i];
        ss += s[i] * s[i];
    }
    float inv = 1.0f / fmaxf(sqrtf(ss), 1e-12f);
#pragma unroll
    for (int i = 0; i < 50; i++) xr[i] = s[i] * inv;

#pragma unroll
    for (int d = 0; d < 10; d++) {
        float t = 0.0f;
#pragma unroll
        for (int g = 0; g < 5; g++)
            t += tqr[g * 10 + d] * tkr[g * 10 + d];
        xr[50 + d] = (t >= 0.0f) ? sqrtf(t) : -sqrtf(-t);
    }
}

// ---------------------------------------------------------------------------
// Contrastive logits: computes 64x64 tiles of G1 = q@q^T and G2 = q@k^T
// together and scatters into logits[2048, 4095] with off-diagonal remap:
//   col 0            = G2[n,n] / T
//   cols 1..2047     = off_diag(G1)[n] / T
//   cols 2048..4094  = off_diag(G2)[n] / T
// ---------------------------------------------------------------------------
__global__ void logits_kernel(const float* __restrict__ q,
                              const float* __restrict__ k,
                              float* __restrict__ out)
{
    __shared__ float Qr[50][64];
    __shared__ float Qc[50][64];
    __shared__ float Kc[50][64];

    const int tid = threadIdx.x;
    const int r0 = blockIdx.y * 64;
    const int c0 = blockIdx.x * 64;

    for (int e = tid; e < 64 * 50; e += 256) {
        int r = e / 50, c = e % 50;
        Qr[c][r] = q[(r0 + r) * 50 + c];
        Qc[c][r] = q[(c0 + r) * 50 + c];
        Kc[c][r] = k[(c0 + r) * 50 + c];
    }
    __syncthreads();

    const int tx = tid & 15;
    const int ty = tid >> 4;

    float g1[4][4], g2[4][4];
#pragma unroll
    for (int i = 0; i < 4; i++)
#pragma unroll
        for (int j = 0; j < 4; j++) { g1[i][j] = 0.0f; g2[i][j] = 0.0f; }

#pragma unroll 2
    for (int c = 0; c < 50; c++) {
        float a[4], bq[4], bk[4];
#pragma unroll
        for (int i = 0; i < 4; i++) a[i]  = Qr[c][ty * 4 + i];
#pragma unroll
        for (int j = 0; j < 4; j++) { bq[j] = Qc[c][tx * 4 + j]; bk[j] = Kc[c][tx * 4 + j]; }
#pragma unroll
        for (int i = 0; i < 4; i++)
#pragma unroll
            for (int j = 0; j < 4; j++) {
                g1[i][j] += a[i] * bq[j];
                g2[i][j] += a[i] * bk[j];
            }
    }

#pragma unroll
    for (int i = 0; i < 4; i++) {
        int n = r0 + ty * 4 + i;
        float* rowp = out + (size_t)n * 4095;
#pragma unroll
        for (int j = 0; j < 4; j++) {
            int m = c0 + tx * 4 + j;
            if (m == n) {
                rowp[0] = g2[i][j] * INV_T;
            } else {
                int off = (m < n) ? m : m - 1;
                rowp[1 + off]    = g1[i][j] * INV_T;
                rowp[2048 + off] = g2[i][j] * INV_T;
            }
        }
    }
}

// ---------------------------------------------------------------------------
// Prototype logits: full = X @ P^T (2048x64), remapped so the can2cluster
// column goes first, remaining 63 in order. Also zeroes both label outputs.
// Block handles 4 rows; thread = (row 0..3, cluster 0..63).
// ---------------------------------------------------------------------------
__global__ void proto_kernel(const float* __restrict__ X,
                             const float* __restrict__ P,
                             const int* __restrict__ c2c,
                             float* __restrict__ lp,
                             float* __restrict__ labels,
                             float* __restrict__ labels_p)
{
    __shared__ float Ps[64][60];
    __shared__ float Xs[4][60];

    const int tid = threadIdx.x;
    const int row0 = blockIdx.x * 4;

    for (int e = tid; e < 64 * 60; e += 256) Ps[e / 60][e % 60] = P[e];
    for (int e = tid; e < 4 * 60; e += 256)
        Xs[e / 60][e % 60] = X[(row0 + e / 60) * 60 + e % 60];
    __syncthreads();

    const int r = tid >> 6;      // 0..3
    const int c = tid & 63;      // 0..63
    const int n = row0 + r;

    float acc = 0.0f;
#pragma unroll
    for (int i = 0; i < 60; i++) acc += Xs[r][i] * Ps[c][i];

    const int cc = c2c[n];
    int pos = (c == cc) ? 0 : ((c < cc) ? c + 1 : c);
    lp[(size_t)n * 64 + pos] = acc;

    if (c == 0) {
        labels[n]   = 0.0f;
        labels_p[n] = 0.0f;
    }
}

// ---------------------------------------------------------------------------
// Launcher
// ---------------------------------------------------------------------------
extern "C" void kernel_launch(void* const* d_in, const int* in_sizes, int n_in,
                              void* d_out, int out_size)
{
    const float* omics_q = (const float*)d_in[0];
    const float* omics_k = (const float*)d_in[1];
    const float* protos  = (const float*)d_in[2];
    const float* re_w1 = (const float*)d_in[3];
    const float* re_b1 = (const float*)d_in[4];
    const float* re_w2 = (const float*)d_in[5];
    const float* re_b2 = (const float*)d_in[6];
    const float* re_w3 = (const float*)d_in[7];
    const float* re_b3 = (const float*)d_in[8];
    const float* rd_w1 = (const float*)d_in[9];
    const float* rd_b1 = (const float*)d_in[10];
    const float* rd_w2 = (const float*)d_in[11];
    const float* rd_b2 = (const float*)d_in[12];
    const float* rd_w3 = (const float*)d_in[13];
    const float* rd_b3 = (const float*)d_in[14];
    const float* me_w1 = (const float*)d_in[15];
    const float* me_b1 = (const float*)d_in[16];
    const float* me_w2 = (const float*)d_in[17];
    const float* me_b2 = (const float*)d_in[18];
    const float* me_w3 = (const float*)d_in[19];
    const float* me_b3 = (const float*)d_in[20];
    const float* md_w1 = (const float*)d_in[21];
    const float* md_b1 = (const float*)d_in[22];
    const float* md_w2 = (const float*)d_in[23];
    const float* md_b2 = (const float*)d_in[24];
    const float* md_w3 = (const float*)d_in[25];
    const float* md_b3 = (const float*)d_in[26];
    const float* lr_w  = (const float*)d_in[27];
    const float* lr_b  = (const float*)d_in[28];
    const float* lm_w  = (const float*)d_in[29];
    const float* lm_b  = (const float*)d_in[30];
    const int*   c2c   = (const int*)d_in[31];

    float* scratch = nullptr;
    cudaGetSymbolAddress((void**)&scratch, g_scratch);

    float* out    = (float*)d_out;
    float* rna    = out;                              // 2048*20000
    float* mirna  = out + 40960000;                   // 2048*2000
    float* logits = out + 45056000;                   // 2048*4095
    float* labels = out + 53442560;                   // 2048
    float* lproto = out + 53444608;                   // 2048*64
    float* lplab  = out + 53575680;                   // 2048

    dim3 blk(256);

    // ---- encoders ----
    sgemm_kernel<<<dim3(4, 32),  blk>>>(omics_q, re_w1, re_b1, scratch + O_Q1, NROWS, 200, D_R, 1);
    sgemm_kernel<<<dim3(4, 32),  blk>>>(omics_k, me_w1, me_b1, scratch + O_K1, NROWS, 200, D_M, 1);
    sgemm_kernel<<<dim3(1, 32),  blk>>>(scratch + O_Q1, re_w2, re_b2, scratch + O_Q2, NROWS, 50, 200, 1);
    sgemm_kernel<<<dim3(1, 32),  blk>>>(scratch + O_K1, me_w2, me_b2, scratch + O_K2, NROWS, 50, 200, 1);
    sgemm_kernel<<<dim3(1, 32),  blk>>>(scratch + O_Q2, re_w3, re_b3, scratch + O_Q,  NROWS, 50, 50, 0);
    sgemm_kernel<<<dim3(1, 32),  blk>>>(scratch + O_K2, me_w3, me_b3, scratch + O_K,  NROWS, 50, 50, 0);

    // ---- decoders ----
    sgemm_kernel<<<dim3(1, 32),   blk>>>(scratch + O_Q,   rd_w1, rd_b1, scratch + O_H1, NROWS, 50, 50, 1);
    sgemm_kernel<<<dim3(4, 32),   blk>>>(scratch + O_H1,  rd_w2, rd_b2, scratch + O_H2, NROWS, 200, 50, 1);
    sgemm_kernel<<<dim3(313, 32), blk>>>(scratch + O_H2,  rd_w3, rd_b3, rna,   NROWS, D_R, 200, 2);
    sgemm_kernel<<<dim3(1, 32),   blk>>>(scratch + O_K,   md_w1, md_b1, scratch + O_HK1, NROWS, 50, 50, 1);
    sgemm_kernel<<<dim3(4, 32),   blk>>>(scratch + O_HK1, md_w2, md_b2, scratch + O_HK2, NROWS, 200, 50, 1);
    sgemm_kernel<<<dim3(32, 32),  blk>>>(scratch + O_HK2, md_w3, md_b3, mirna, NROWS, D_M, 200, 2);

    // ---- bilinear / fused X ----
    sgemm_kernel<<<dim3(1, 32), blk>>>(scratch + O_Q, lr_w, lr_b, scratch + O_TQ, NROWS, 50, 50, 0);
    sgemm_kernel<<<dim3(1, 32), blk>>>(scratch + O_K, lm_w, lm_b, scratch + O_TK, NROWS, 50, 50, 0);
    fuse_X_kernel<<<16, 128>>>(scratch + O_Q, scratch + O_K,
                               scratch + O_TQ, scratch + O_TK, scratch + O_X);

    // ---- contrastive logits ----
    logits_kernel<<<dim3(32, 32), blk>>>(scratch + O_Q, scratch + O_K, logits);

    // ---- prototype logits + labels ----
    proto_kernel<<<512, blk>>>(scratch + O_X, protos, c2c, lproto, labels, lplab);
}

// round 6
// speedup vs baseline: 1.3037x; 1.3037x over previous
#include <cuda_runtime.h>
#include <math.h>

typedef unsigned long long ull;

// ---------------------------------------------------------------------------
// Problem constants
// ---------------------------------------------------------------------------
#define NROWS 2048
#define D_R   20000
#define D_M   2000
#define INV_T 5.0f   // 1/0.2

// scratch layout (floats)
#define O_Q1   0          // 2048*200
#define O_K1   409600
#define O_Q2   819200     // 2048*50
#define O_K2   921600
#define O_Q    1024000
#define O_K    1126400
#define O_H1   1228800
#define O_H2   1331200    // 2048*200
#define O_HK1  1740800
#define O_HK2  1843200    // 2048*200
#define O_TQ   2252800
#define O_TK   2355200
#define O_X    2457600    // 2048*60
#define O_PQ   2580480    // 4 * 2048*200 split-K partials (q)
#define O_PK   4218880    // 4 * 2048*200 split-K partials (k)
#define SCRATCH_FLOATS 5857280

static __device__ float g_scratch[SCRATCH_FLOATS];

// ---------------------------------------------------------------------------
// Packed f32x2 helpers (Blackwell FFMA2 — only reachable via PTX)
// ---------------------------------------------------------------------------
__device__ __forceinline__ ull pack_dup(float a) {
    ull d;
    asm("mov.b64 %0, {%1, %1};" : "=l"(d) : "f"(a));
    return d;
}
__device__ __forceinline__ void fma2(ull& c, ull a, ull b) {
    asm("fma.rn.f32x2 %0, %1, %2, %3;" : "=l"(c) : "l"(a), "l"(b), "l"(c));
}
__device__ __forceinline__ float2 unpack2(ull v) {
    float lo, hi;
    asm("mov.b64 {%0, %1}, %2;" : "=f"(lo), "=f"(hi) : "l"(v));
    return make_float2(lo, hi);
}

// ---------------------------------------------------------------------------
// Core tiled GEMM, 64x64 tile, BK=16, 256 threads, 4x4 outputs/thread,
// inner product done with packed f32x2 FMA (2 MACs / instruction).
// act: 0 = none, 1 = relu, 2 = sigmoid.  partial => raw store, no bias/act.
// ---------------------------------------------------------------------------
#define BM 64
#define BN 64
#define BK 16

__device__ __forceinline__ void gemm_core(const float* __restrict__ A,
                                          const float* __restrict__ B,
                                          const float* __restrict__ bias,
                                          float* __restrict__ C,
                                          int M, int N, int K, int act,
                                          int kStart, int kEnd, bool partial)
{
    __shared__ __align__(16) float As[BK][BM];
    __shared__ __align__(16) float Bs[BK][BN];

    const int tid  = threadIdx.x;
    const int row0 = blockIdx.y * BM;
    const int col0 = blockIdx.x * BN;
    const int tx = tid & 15;
    const int ty = tid >> 4;

    ull acc[4][2] = {};   // 4 rows x 2 packed col-pairs = 4x4 floats

    for (int k0 = kStart; k0 < kEnd; k0 += BK) {
        // A tile (64 x 16) -> As[k][m]
#pragma unroll
        for (int l = 0; l < 4; l++) {
            int e  = tid + l * 256;
            int m  = e / BK;
            int kk = e % BK;
            int gr = row0 + m;
            int gk = k0 + kk;
            As[kk][m] = (gr < M && gk < kEnd) ? A[(size_t)gr * K + gk] : 0.0f;
        }
        // B tile (16 x 64)
#pragma unroll
        for (int l = 0; l < 4; l++) {
            int e  = tid + l * 256;
            int kk = e / BN;
            int n  = e % BN;
            int gk = k0 + kk;
            int gc = col0 + n;
            Bs[kk][n] = (gk < kEnd && gc < N) ? B[(size_t)gk * N + gc] : 0.0f;
        }
        __syncthreads();

#pragma unroll
        for (int kk = 0; kk < BK; kk++) {
            ull bp0 = *(const ull*)&Bs[kk][tx * 4];
            ull bp1 = *(const ull*)&Bs[kk][tx * 4 + 2];
#pragma unroll
            for (int i = 0; i < 4; i++) {
                ull ad = pack_dup(As[kk][ty * 4 + i]);
                fma2(acc[i][0], ad, bp0);
                fma2(acc[i][1], ad, bp1);
            }
        }
        __syncthreads();
    }

#pragma unroll
    for (int i = 0; i < 4; i++) {
        int r = row0 + ty * 4 + i;
        if (r >= M) continue;
        float2 p0 = unpack2(acc[i][0]);
        float2 p1 = unpack2(acc[i][1]);
        float vals[4] = {p0.x, p0.y, p1.x, p1.y};
#pragma unroll
        for (int j = 0; j < 4; j++) {
            int c = col0 + tx * 4 + j;
            if (c >= N) continue;
            float v = vals[j];
            if (!partial) {
                v += bias[c];
                if (act == 1)      v = fmaxf(v, 0.0f);
                else if (act == 2) v = 1.0f / (1.0f + __expf(-v));
            }
            C[(size_t)r * N + c] = v;
        }
    }
}

// full-K GEMM with bias + activation
__global__ void sgemm_act(const float* __restrict__ A, const float* __restrict__ B,
                          const float* __restrict__ bias, float* __restrict__ C,
                          int M, int N, int K, int act)
{
    gemm_core(A, B, bias, C, M, N, K, act, 0, K, false);
}

// split-K GEMM: blockIdx.z selects K chunk, writes raw partial to C + z*M*N
__global__ void sgemm_splitk(const float* __restrict__ A, const float* __restrict__ B,
                             float* __restrict__ C, int M, int N, int K, int chunk)
{
    int z  = blockIdx.z;
    int ks = z * chunk;
    int ke = ks + chunk; if (ke > K) ke = K;
    gemm_core(A, B, nullptr, C + (size_t)z * M * N, M, N, K, 0, ks, ke, true);
}

// z-batched GEMM: up to 4 independent jobs sharing (M, N, K)
struct GemmJobs {
    const float* A[4];
    const float* B[4];
    const float* bias[4];
    float*       C[4];
    int          act[4];
};
__global__ void sgemm_batch(GemmJobs jobs, int M, int N, int K)
{
    int j = blockIdx.z;
    gemm_core(jobs.A[j], jobs.B[j], jobs.bias[j], jobs.C[j],
              M, N, K, jobs.act[j], 0, K, false);
}

// ---------------------------------------------------------------------------
// Split-K reduction (4 partials) + bias + relu, batched over 2 jobs.
// N must be a multiple of 4 (N=200).
// ---------------------------------------------------------------------------
struct RedJobs {
    const float* P[2];
    const float* bias[2];
    float*       C[2];
};
__global__ void reduce_splitk4(RedJobs jobs, int M, int N)
{
    int j = blockIdx.z;
    int idx = blockIdx.x * blockDim.x + threadIdx.x;   // float4 index
    int total = (M * N) >> 2;
    if (idx >= total) return;

    const float4* P = (const float4*)jobs.P[j];
    float4 s = P[idx];
    float4 a = P[idx + total];
    float4 b = P[idx + 2 * total];
    float4 c = P[idx + 3 * total];
    s.x += a.x + b.x + c.x;
    s.y += a.y + b.y + c.y;
    s.z += a.z + b.z + c.z;
    s.w += a.w + b.w + c.w;

    int col = (idx * 4) % N;
    const float* bi = jobs.bias[j] + col;
    s.x = fmaxf(s.x + bi[0], 0.0f);
    s.y = fmaxf(s.y + bi[1], 0.0f);
    s.z = fmaxf(s.z + bi[2], 0.0f);
    s.w = fmaxf(s.w + bi[3], 0.0f);

    ((float4*)jobs.C[j])[idx] = s;
}

// ---------------------------------------------------------------------------
// Per-row fusion: s = q+k, s_n = s/max(||s||,1e-12),
// t[d] = sum_g tq[g*10+d]*tk[g*10+d], fbn = sqrt(relu(t))-sqrt(relu(-t))
// X = [s_n (50) | fbn (10)]
// ---------------------------------------------------------------------------
__global__ void fuse_X_kernel(const float* __restrict__ q,
                              const float* __restrict__ k,
                              const float* __restrict__ tq,
                              const float* __restrict__ tk,
                              float* __restrict__ X)
{
    int row = blockIdx.x * blockDim.x + threadIdx.x;
    if (row >= NROWS) return;

    const float* qr  = q  + row * 50;
    const float* kr  = k  + row * 50;
    const float* tqr = tq + row * 50;
    const float* tkr = tk + row * 50;
    float* xr = X + row * 60;

    float s[50];
    float ss = 0.0f;
#pragma unroll
    for (int i = 0; i < 50; i++) {
        s[i] = qr[i] + kr[i];
        ss += s[i] * s[i];
    }
    float inv = 1.0f / fmaxf(sqrtf(ss), 1e-12f);
#pragma unroll
    for (int i = 0; i < 50; i++) xr[i] = s[i] * inv;

#pragma unroll
    for (int d = 0; d < 10; d++) {
        float t = 0.0f;
#pragma unroll
        for (int g = 0; g < 5; g++)
            t += tqr[g * 10 + d] * tkr[g * 10 + d];
        xr[50 + d] = (t >= 0.0f) ? sqrtf(t) : -sqrtf(-t);
    }
}

// ---------------------------------------------------------------------------
// Contrastive logits: 64x64 tiles of G1 = q@q^T and G2 = q@k^T together,
// scattered into logits[2048, 4095] with off-diagonal remap. Packed f32x2.
// ---------------------------------------------------------------------------
__global__ void logits_kernel(const float* __restrict__ q,
                              const float* __restrict__ k,
                              float* __restrict__ out)
{
    __shared__ __align__(16) float Qr[50][64];
    __shared__ __align__(16) float Qc[50][64];
    __shared__ __align__(16) float Kc[50][64];

    const int tid = threadIdx.x;
    const int r0 = blockIdx.y * 64;
    const int c0 = blockIdx.x * 64;

    for (int e = tid; e < 64 * 50; e += 256) {
        int r = e / 50, c = e % 50;
        Qr[c][r] = q[(r0 + r) * 50 + c];
        Qc[c][r] = q[(c0 + r) * 50 + c];
        Kc[c][r] = k[(c0 + r) * 50 + c];
    }
    __syncthreads();

    const int tx = tid & 15;
    const int ty = tid >> 4;

    ull g1[4][2] = {};
    ull g2[4][2] = {};

#pragma unroll 2
    for (int c = 0; c < 50; c++) {
        ull bq0 = *(const ull*)&Qc[c][tx * 4];
        ull bq1 = *(const ull*)&Qc[c][tx * 4 + 2];
        ull bk0 = *(const ull*)&Kc[c][tx * 4];
        ull bk1 = *(const ull*)&Kc[c][tx * 4 + 2];
#pragma unroll
        for (int i = 0; i < 4; i++) {
            ull ad = pack_dup(Qr[c][ty * 4 + i]);
            fma2(g1[i][0], ad, bq0);
            fma2(g1[i][1], ad, bq1);
            fma2(g2[i][0], ad, bk0);
            fma2(g2[i][1], ad, bk1);
        }
    }

#pragma unroll
    for (int i = 0; i < 4; i++) {
        int n = r0 + ty * 4 + i;
        float* rowp = out + (size_t)n * 4095;
        float2 a0 = unpack2(g1[i][0]), a1 = unpack2(g1[i][1]);
        float2 b0 = unpack2(g2[i][0]), b1 = unpack2(g2[i][1]);
        float v1[4] = {a0.x, a0.y, a1.x, a1.y};
        float v2[4] = {b0.x, b0.y, b1.x, b1.y};
#pragma unroll
        for (int j = 0; j < 4; j++) {
            int m = c0 + tx * 4 + j;
            if (m == n) {
                rowp[0] = v2[j] * INV_T;
            } else {
                int off = (m < n) ? m : m - 1;
                rowp[1 + off]    = v1[j] * INV_T;
                rowp[2048 + off] = v2[j] * INV_T;
            }
        }
    }
}

// ---------------------------------------------------------------------------
// Prototype logits + label zeroing.
// ---------------------------------------------------------------------------
__global__ void proto_kernel(const float* __restrict__ X,
                             const float* __restrict__ P,
                             const int* __restrict__ c2c,
                             float* __restrict__ lp,
                             float* __restrict__ labels,
                             float* __restrict__ labels_p)
{
    __shared__ float Ps[64][60];
    __shared__ float Xs[4][60];

    const int tid = threadIdx.x;
    const int row0 = blockIdx.x * 4;

    for (int e = tid; e < 64 * 60; e += 256) Ps[e / 60][e % 60] = P[e];
    for (int e = tid; e < 4 * 60; e += 256)
        Xs[e / 60][e % 60] = X[(row0 + e / 60) * 60 + e % 60];
    __syncthreads();

    const int r = tid >> 6;      // 0..3
    const int c = tid & 63;      // 0..63
    const int n = row0 + r;

    float acc = 0.0f;
#pragma unroll
    for (int i = 0; i < 60; i++) acc += Xs[r][i] * Ps[c][i];

    const int cc = c2c[n];
    int pos = (c == cc) ? 0 : ((c < cc) ? c + 1 : c);
    lp[(size_t)n * 64 + pos] = acc;

    if (c == 0) {
        labels[n]   = 0.0f;
        labels_p[n] = 0.0f;
    }
}

// ---------------------------------------------------------------------------
// Launcher
// ---------------------------------------------------------------------------
extern "C" void kernel_launch(void* const* d_in, const int* in_sizes, int n_in,
                              void* d_out, int out_size)
{
    const float* omics_q = (const float*)d_in[0];
    const float* omics_k = (const float*)d_in[1];
    const float* protos  = (const float*)d_in[2];
    const float* re_w1 = (const float*)d_in[3];
    const float* re_b1 = (const float*)d_in[4];
    const float* re_w2 = (const float*)d_in[5];
    const float* re_b2 = (const float*)d_in[6];
    const float* re_w3 = (const float*)d_in[7];
    const float* re_b3 = (const float*)d_in[8];
    const float* rd_w1 = (const float*)d_in[9];
    const float* rd_b1 = (const float*)d_in[10];
    const float* rd_w2 = (const float*)d_in[11];
    const float* rd_b2 = (const float*)d_in[12];
    const float* rd_w3 = (const float*)d_in[13];
    const float* rd_b3 = (const float*)d_in[14];
    const float* me_w1 = (const float*)d_in[15];
    const float* me_b1 = (const float*)d_in[16];
    const float* me_w2 = (const float*)d_in[17];
    const float* me_b2 = (const float*)d_in[18];
    const float* me_w3 = (const float*)d_in[19];
    const float* me_b3 = (const float*)d_in[20];
    const float* md_w1 = (const float*)d_in[21];
    const float* md_b1 = (const float*)d_in[22];
    const float* md_w2 = (const float*)d_in[23];
    const float* md_b2 = (const float*)d_in[24];
    const float* md_w3 = (const float*)d_in[25];
    const float* md_b3 = (const float*)d_in[26];
    const float* lr_w  = (const float*)d_in[27];
    const float* lr_b  = (const float*)d_in[28];
    const float* lm_w  = (const float*)d_in[29];
    const float* lm_b  = (const float*)d_in[30];
    const int*   c2c   = (const int*)d_in[31];

    float* scratch = nullptr;
    cudaGetSymbolAddress((void**)&scratch, g_scratch);

    float* out    = (float*)d_out;
    float* rna    = out;                              // 2048*20000
    float* mirna  = out + 40960000;                   // 2048*2000
    float* logits = out + 45056000;                   // 2048*4095
    float* labels = out + 53442560;                   // 2048
    float* lproto = out + 53444608;                   // 2048*64
    float* lplab  = out + 53575680;                   // 2048

    dim3 blk(256);

    // ---- encoders L1 (the two big-K GEMMs): split-K=4 to fill the chip ----
    sgemm_splitk<<<dim3(4, 32, 4), blk>>>(omics_q, re_w1, scratch + O_PQ,
                                          NROWS, 200, D_R, 5008);
    sgemm_splitk<<<dim3(4, 32, 4), blk>>>(omics_k, me_w1, scratch + O_PK,
                                          NROWS, 200, D_M, 512);
    {
        RedJobs rj;
        rj.P[0] = scratch + O_PQ;  rj.bias[0] = re_b1;  rj.C[0] = scratch + O_Q1;
        rj.P[1] = scratch + O_PK;  rj.bias[1] = me_b1;  rj.C[1] = scratch + O_K1;
        reduce_splitk4<<<dim3(400, 1, 2), blk>>>(rj, NROWS, 200);
    }

    // ---- encoders L2 (batched q/k) ----
    {
        GemmJobs j;
        j.A[0] = scratch + O_Q1; j.B[0] = re_w2; j.bias[0] = re_b2; j.C[0] = scratch + O_Q2; j.act[0] = 1;
        j.A[1] = scratch + O_K1; j.B[1] = me_w2; j.bias[1] = me_b2; j.C[1] = scratch + O_K2; j.act[1] = 1;
        sgemm_batch<<<dim3(1, 32, 2), blk>>>(j, NROWS, 50, 200);
    }
    // ---- encoders L3 (batched q/k) ----
    {
        GemmJobs j;
        j.A[0] = scratch + O_Q2; j.B[0] = re_w3; j.bias[0] = re_b3; j.C[0] = scratch + O_Q; j.act[0] = 0;
        j.A[1] = scratch + O_K2; j.B[1] = me_w3; j.bias[1] = me_b3; j.C[1] = scratch + O_K; j.act[1] = 0;
        sgemm_batch<<<dim3(1, 32, 2), blk>>>(j, NROWS, 50, 50);
    }
    // ---- decoder L1 (q,k) + bilinear tq,tk: 4 jobs, all 2048x50x50 ----
    {
        GemmJobs j;
        j.A[0] = scratch + O_Q; j.B[0] = rd_w1; j.bias[0] = rd_b1; j.C[0] = scratch + O_H1;  j.act[0] = 1;
        j.A[1] = scratch + O_K; j.B[1] = md_w1; j.bias[1] = md_b1; j.C[1] = scratch + O_HK1; j.act[1] = 1;
        j.A[2] = scratch + O_Q; j.B[2] = lr_w;  j.bias[2] = lr_b;  j.C[2] = scratch + O_TQ;  j.act[2] = 0;
        j.A[3] = scratch + O_K; j.B[3] = lm_w;  j.bias[3] = lm_b;  j.C[3] = scratch + O_TK;  j.act[3] = 0;
        sgemm_batch<<<dim3(1, 32, 4), blk>>>(j, NROWS, 50, 50);
    }
    // ---- decoder L2 (batched q/k) ----
    {
        GemmJobs j;
        j.A[0] = scratch + O_H1;  j.B[0] = rd_w2; j.bias[0] = rd_b2; j.C[0] = scratch + O_H2;  j.act[0] = 1;
        j.A[1] = scratch + O_HK1; j.B[1] = md_w2; j.bias[1] = md_b2; j.C[1] = scratch + O_HK2; j.act[1] = 1;
        sgemm_batch<<<dim3(4, 32, 2), blk>>>(j, NROWS, 200, 50);
    }

    // ---- decoder L3 (big-N GEMMs, sigmoid) ----
    sgemm_act<<<dim3(313, 32), blk>>>(scratch + O_H2,  rd_w3, rd_b3, rna,   NROWS, D_R, 200, 2);
    sgemm_act<<<dim3(32, 32),  blk>>>(scratch + O_HK2, md_w3, md_b3, mirna, NROWS, D_M, 200, 2);

    // ---- fused X ----
    fuse_X_kernel<<<16, 128>>>(scratch + O_Q, scratch + O_K,
                               scratch + O_TQ, scratch + O_TK, scratch + O_X);

    // ---- contrastive logits ----
    logits_kernel<<<dim3(32, 32), blk>>>(scratch + O_Q, scratch + O_K, logits);

    // ---- prototype logits + labels ----
    proto_kernel<<<512, blk>>>(scratch + O_X, protos, c2c, lproto, labels, lplab);
}

// round 7
// speedup vs baseline: 2.4514x; 1.8803x over previous
#include <cuda_runtime.h>
#include <math.h>

typedef unsigned long long ull;

// ---------------------------------------------------------------------------
// Problem constants
// ---------------------------------------------------------------------------
#define NROWS 2048
#define D_R   20000
#define D_M   2000
#define INV_T 5.0f   // 1/0.2
#define ZSPLIT 8

// scratch layout (floats)
#define O_Q1   0          // 2048*200
#define O_K1   409600
#define O_Q2   819200     // 2048*50
#define O_K2   921600
#define O_Q    1024000
#define O_K    1126400
#define O_H1   1228800
#define O_H2   1331200    // 2048*200
#define O_HK1  1740800
#define O_HK2  1843200    // 2048*200
#define O_TQ   2252800
#define O_TK   2355200
#define O_X    2457600    // 2048*60
#define O_PQ   2580480    // 8 * 2048*200 split-K partials (q)
#define O_PK   5857280    // 8 * 2048*200 split-K partials (k)
#define SCRATCH_FLOATS 9134080

static __device__ float g_scratch[SCRATCH_FLOATS];

// ---------------------------------------------------------------------------
// Packed f32x2 helpers (Blackwell FFMA2 — only reachable via PTX)
// ---------------------------------------------------------------------------
__device__ __forceinline__ ull pack_dup(float a) {
    ull d;
    asm("mov.b64 %0, {%1, %1};" : "=l"(d) : "f"(a));
    return d;
}
__device__ __forceinline__ void fma2(ull& c, ull a, ull b) {
    asm("fma.rn.f32x2 %0, %1, %2, %3;" : "=l"(c) : "l"(a), "l"(b), "l"(c));
}
__device__ __forceinline__ float2 unpack2(ull v) {
    float lo, hi;
    asm("mov.b64 {%0, %1}, %2;" : "=f"(lo), "=f"(hi) : "l"(v));
    return make_float2(lo, hi);
}

// ===========================================================================
// BIG GEMM: 128x64 tile, BK=16, 256 threads, 8x4 per thread.
// Accumulators packed along M (f32x2 pairs of adjacent rows) -> A read from
// SMEM directly as packed pairs (no MOV), only 4 B pack_dups per k-step.
// Double-buffered SMEM, register prefetch, ONE barrier per tile.
// Requires M % 128 == 0 (true here: M = 2048 always).
// ===========================================================================
#define GBM 128
#define GBN 64
#define GBK 16
#define APAD 132   // As row stride in floats (128 + 4, conflict reduction)

__device__ __forceinline__ float4 ldgA_guard(const float* p, int k, int kEnd) {
    if (k + 3 < kEnd) return *(const float4*)p;
    float4 v = make_float4(0.f, 0.f, 0.f, 0.f);
    if (k     < kEnd) v.x = p[0];
    if (k + 1 < kEnd) v.y = p[1];
    if (k + 2 < kEnd) v.z = p[2];
    if (k + 3 < kEnd) v.w = p[3];
    return v;
}
__device__ __forceinline__ float4 ldgB_guard(const float* p, int krow, int kEnd,
                                             int col, int N) {
    float4 v = make_float4(0.f, 0.f, 0.f, 0.f);
    if (krow < kEnd) {
        if (col + 3 < N) return *(const float4*)p;
        if (col     < N) v.x = p[0];
        if (col + 1 < N) v.y = p[1];
        if (col + 2 < N) v.z = p[2];
        if (col + 3 < N) v.w = p[3];
    }
    return v;
}

__device__ __forceinline__ void bgemm_core(const float* __restrict__ A,
                                           const float* __restrict__ B,
                                           const float* __restrict__ bias,
                                           float* __restrict__ C,
                                           int M, int N, int K, int act,
                                           int kStart, int kEnd, bool partial)
{
    __shared__ __align__(16) float As[2][GBK][APAD];
    __shared__ __align__(16) float Bs[2][GBK][GBN];

    const int tid  = threadIdx.x;
    const int row0 = blockIdx.y * GBM;
    const int col0 = blockIdx.x * GBN;
    const int tx = tid & 15;    // 4 cols each: col0 + tx*4 + j
    const int ty = tid >> 4;    // 8 rows each: row0 + ty*8 + (0..7)

    // A chunk mapping: e = tid + l*256 (l=0,1); m = e>>2 (0..127), kc = e&3
    const int am  = tid >> 2;
    const int akc = tid & 3;
    // B chunk mapping: kk = tid>>4 (0..15), nc = tid&15 (4 cols)
    const int bkk = tid >> 4;
    const int bnc = tid & 15;

    ull acc[4][4] = {};   // [m-pair 0..3][col 0..3]

    const int nT = (kEnd - kStart + GBK - 1) / GBK;

    float4 pa0, pa1, pb;
    {
        int k0 = kStart;
        int ka = k0 + akc * 4;
        pa0 = ldgA_guard(A + (size_t)(row0 + am)       * K + ka, ka, kEnd);
        pa1 = ldgA_guard(A + (size_t)(row0 + am + 64)  * K + ka, ka, kEnd);
        int kb = k0 + bkk, cb = col0 + bnc * 4;
        pb  = ldgB_guard(B + (size_t)kb * N + cb, kb, kEnd, cb, N);
    }

    int buf = 0;
    for (int t = 0; t < nT; t++) {
        // stage prefetched tile into smem[buf]
        As[buf][akc * 4 + 0][am] = pa0.x;
        As[buf][akc * 4 + 1][am] = pa0.y;
        As[buf][akc * 4 + 2][am] = pa0.z;
        As[buf][akc * 4 + 3][am] = pa0.w;
        As[buf][akc * 4 + 0][am + 64] = pa1.x;
        As[buf][akc * 4 + 1][am + 64] = pa1.y;
        As[buf][akc * 4 + 2][am + 64] = pa1.z;
        As[buf][akc * 4 + 3][am + 64] = pa1.w;
        *(float4*)&Bs[buf][bkk][bnc * 4] = pb;
        __syncthreads();

        if (t + 1 < nT) {
            int k0 = kStart + (t + 1) * GBK;
            int ka = k0 + akc * 4;
            pa0 = ldgA_guard(A + (size_t)(row0 + am)      * K + ka, ka, kEnd);
            pa1 = ldgA_guard(A + (size_t)(row0 + am + 64) * K + ka, ka, kEnd);
            int kb = k0 + bkk, cb = col0 + bnc * 4;
            pb  = ldgB_guard(B + (size_t)kb * N + cb, kb, kEnd, cb, N);
        }

#pragma unroll
        for (int kk = 0; kk < GBK; kk++) {
            // A: 8 rows as 4 packed f32x2 pairs — no MOVs, warp-broadcast LDS
            longlong2 A0 = *(const longlong2*)&As[buf][kk][ty * 8];
            longlong2 A1 = *(const longlong2*)&As[buf][kk][ty * 8 + 4];
            ull ap0 = (ull)A0.x, ap1 = (ull)A0.y;
            ull ap2 = (ull)A1.x, ap3 = (ull)A1.y;
#pragma unroll
            for (int j = 0; j < 4; j++) {
                ull bd = pack_dup(Bs[buf][kk][tx * 4 + j]);
                fma2(acc[0][j], ap0, bd);
                fma2(acc[1][j], ap1, bd);
                fma2(acc[2][j], ap2, bd);
                fma2(acc[3][j], ap3, bd);
            }
        }
        buf ^= 1;
        // NOTE: single barrier per tile is race-free — a thread can be at most
        // one barrier ahead, and adjacent iterations touch different buffers.
    }

#pragma unroll
    for (int p = 0; p < 4; p++) {
        int r = row0 + ty * 8 + 2 * p;
#pragma unroll
        for (int j = 0; j < 4; j++) {
            int c = col0 + tx * 4 + j;
            if (c >= N) continue;
            float2 v = unpack2(acc[p][j]);
            if (!partial) {
                float bb = bias[c];
                v.x += bb; v.y += bb;
                if (act == 1)      { v.x = fmaxf(v.x, 0.f); v.y = fmaxf(v.y, 0.f); }
                else if (act == 2) { v.x = 1.f / (1.f + __expf(-v.x));
                                     v.y = 1.f / (1.f + __expf(-v.y)); }
            }
            C[(size_t)r * N + c]       = v.x;
            C[(size_t)(r + 1) * N + c] = v.y;
        }
    }
}

__global__ void __launch_bounds__(256, 3)
bgemm_splitk(const float* __restrict__ A, const float* __restrict__ B,
             float* __restrict__ C, int M, int N, int K, int chunk)
{
    int z  = blockIdx.z;
    int ks = z * chunk;
    int ke = ks + chunk; if (ke > K) ke = K;
    bgemm_core(A, B, nullptr, C + (size_t)z * M * N, M, N, K, 0, ks, ke, true);
}

__global__ void __launch_bounds__(256, 3)
bgemm_act(const float* __restrict__ A, const float* __restrict__ B,
          const float* __restrict__ bias, float* __restrict__ C,
          int M, int N, int K, int act)
{
    bgemm_core(A, B, bias, C, M, N, K, act, 0, K, false);
}

// ---------------------------------------------------------------------------
// Small tiled GEMM (64x64, f32x2), used for the 50/200-dim chain.
// ---------------------------------------------------------------------------
#define BM 64
#define BN 64
#define BK 16

__device__ __forceinline__ void gemm_core(const float* __restrict__ A,
                                          const float* __restrict__ B,
                                          const float* __restrict__ bias,
                                          float* __restrict__ C,
                                          int M, int N, int K, int act)
{
    __shared__ __align__(16) float As[BK][BM];
    __shared__ __align__(16) float Bs[BK][BN];

    const int tid  = threadIdx.x;
    const int row0 = blockIdx.y * BM;
    const int col0 = blockIdx.x * BN;
    const int tx = tid & 15;
    const int ty = tid >> 4;

    ull acc[4][2] = {};

    for (int k0 = 0; k0 < K; k0 += BK) {
#pragma unroll
        for (int l = 0; l < 4; l++) {
            int e  = tid + l * 256;
            int m  = e / BK;
            int kk = e % BK;
            int gr = row0 + m;
            int gk = k0 + kk;
            As[kk][m] = (gr < M && gk < K) ? A[(size_t)gr * K + gk] : 0.0f;
        }
#pragma unroll
        for (int l = 0; l < 4; l++) {
            int e  = tid + l * 256;
            int kk = e / BN;
            int n  = e % BN;
            int gk = k0 + kk;
            int gc = col0 + n;
            Bs[kk][n] = (gk < K && gc < N) ? B[(size_t)gk * N + gc] : 0.0f;
        }
        __syncthreads();

#pragma unroll
        for (int kk = 0; kk < BK; kk++) {
            ull bp0 = *(const ull*)&Bs[kk][tx * 4];
            ull bp1 = *(const ull*)&Bs[kk][tx * 4 + 2];
#pragma unroll
            for (int i = 0; i < 4; i++) {
                ull ad = pack_dup(As[kk][ty * 4 + i]);
                fma2(acc[i][0], ad, bp0);
                fma2(acc[i][1], ad, bp1);
            }
        }
        __syncthreads();
    }

#pragma unroll
    for (int i = 0; i < 4; i++) {
        int r = row0 + ty * 4 + i;
        if (r >= M) continue;
        float2 p0 = unpack2(acc[i][0]);
        float2 p1 = unpack2(acc[i][1]);
        float vals[4] = {p0.x, p0.y, p1.x, p1.y};
#pragma unroll
        for (int j = 0; j < 4; j++) {
            int c = col0 + tx * 4 + j;
            if (c >= N) continue;
            float v = vals[j] + bias[c];
            if (act == 1)      v = fmaxf(v, 0.0f);
            else if (act == 2) v = 1.0f / (1.0f + __expf(-v));
            C[(size_t)r * N + c] = v;
        }
    }
}

struct GemmJobs {
    const float* A[4];
    const float* B[4];
    const float* bias[4];
    float*       C[4];
    int          act[4];
};
__global__ void sgemm_batch(GemmJobs jobs, int M, int N, int K)
{
    int j = blockIdx.z;
    gemm_core(jobs.A[j], jobs.B[j], jobs.bias[j], jobs.C[j],
              M, N, K, jobs.act[j]);
}

// ---------------------------------------------------------------------------
// Split-K reduction (ZSPLIT partials) + bias + relu, batched over 2 jobs.
// ---------------------------------------------------------------------------
struct RedJobs {
    const float* P[2];
    const float* bias[2];
    float*       C[2];
};
__global__ void reduce_splitk(RedJobs jobs, int M, int N)
{
    int j = blockIdx.z;
    int idx = blockIdx.x * blockDim.x + threadIdx.x;   // float4 index
    int total = (M * N) >> 2;
    if (idx >= total) return;

    const float4* P = (const float4*)jobs.P[j];
    float4 s = P[idx];
#pragma unroll
    for (int z = 1; z < ZSPLIT; z++) {
        float4 a = P[idx + (size_t)z * total];
        s.x += a.x; s.y += a.y; s.z += a.z; s.w += a.w;
    }

    int col = (idx * 4) % N;
    const float* bi = jobs.bias[j] + col;
    s.x = fmaxf(s.x + bi[0], 0.0f);
    s.y = fmaxf(s.y + bi[1], 0.0f);
    s.z = fmaxf(s.z + bi[2], 0.0f);
    s.w = fmaxf(s.w + bi[3], 0.0f);

    ((float4*)jobs.C[j])[idx] = s;
}

// ---------------------------------------------------------------------------
// Per-row fusion: X = [ (q+k)/||q+k|| (50) | fbn (10) ]
// ---------------------------------------------------------------------------
__global__ void fuse_X_kernel(const float* __restrict__ q,
                              const float* __restrict__ k,
                              const float* __restrict__ tq,
                              const float* __restrict__ tk,
                              float* __restrict__ X)
{
    int row = blockIdx.x * blockDim.x + threadIdx.x;
    if (row >= NROWS) return;

    const float* qr  = q  + row * 50;
    const float* kr  = k  + row * 50;
    const float* tqr = tq + row * 50;
    const float* tkr = tk + row * 50;
    float* xr = X + row * 60;

    float s[50];
    float ss = 0.0f;
#pragma unroll
    for (int i = 0; i < 50; i++) {
        s[i] = qr[i] + kr[i];
        ss += s[i] * s[i];
    }
    float inv = 1.0f / fmaxf(sqrtf(ss), 1e-12f);
#pragma unroll
    for (int i = 0; i < 50; i++) xr[i] = s[i] * inv;

#pragma unroll
    for (int d = 0; d < 10; d++) {
        float t = 0.0f;
#pragma unroll
        for (int g = 0; g < 5; g++)
            t += tqr[g * 10 + d] * tkr[g * 10 + d];
        xr[50 + d] = (t >= 0.0f) ? sqrtf(t) : -sqrtf(-t);
    }
}

// ---------------------------------------------------------------------------
// Contrastive logits with off-diagonal remap (G1=q@q^T and G2=q@k^T jointly)
// ---------------------------------------------------------------------------
__global__ void logits_kernel(const float* __restrict__ q,
                              const float* __restrict__ k,
                              float* __restrict__ out)
{
    __shared__ __align__(16) float Qr[50][64];
    __shared__ __align__(16) float Qc[50][64];
    __shared__ __align__(16) float Kc[50][64];

    const int tid = threadIdx.x;
    const int r0 = blockIdx.y * 64;
    const int c0 = blockIdx.x * 64;

    for (int e = tid; e < 64 * 50; e += 256) {
        int r = e / 50, c = e % 50;
        Qr[c][r] = q[(r0 + r) * 50 + c];
        Qc[c][r] = q[(c0 + r) * 50 + c];
        Kc[c][r] = k[(c0 + r) * 50 + c];
    }
    __syncthreads();

    const int tx = tid & 15;
    const int ty = tid >> 4;

    ull g1[4][2] = {};
    ull g2[4][2] = {};

#pragma unroll 2
    for (int c = 0; c < 50; c++) {
        ull bq0 = *(const ull*)&Qc[c][tx * 4];
        ull bq1 = *(const ull*)&Qc[c][tx * 4 + 2];
        ull bk0 = *(const ull*)&Kc[c][tx * 4];
        ull bk1 = *(const ull*)&Kc[c][tx * 4 + 2];
#pragma unroll
        for (int i = 0; i < 4; i++) {
            ull ad = pack_dup(Qr[c][ty * 4 + i]);
            fma2(g1[i][0], ad, bq0);
            fma2(g1[i][1], ad, bq1);
            fma2(g2[i][0], ad, bk0);
            fma2(g2[i][1], ad, bk1);
        }
    }

#pragma unroll
    for (int i = 0; i < 4; i++) {
        int n = r0 + ty * 4 + i;
        float* rowp = out + (size_t)n * 4095;
        float2 a0 = unpack2(g1[i][0]), a1 = unpack2(g1[i][1]);
        float2 b0 = unpack2(g2[i][0]), b1 = unpack2(g2[i][1]);
        float v1[4] = {a0.x, a0.y, a1.x, a1.y};
        float v2[4] = {b0.x, b0.y, b1.x, b1.y};
#pragma unroll
        for (int j = 0; j < 4; j++) {
            int m = c0 + tx * 4 + j;
            if (m == n) {
                rowp[0] = v2[j] * INV_T;
            } else {
                int off = (m < n) ? m : m - 1;
                rowp[1 + off]    = v1[j] * INV_T;
                rowp[2048 + off] = v2[j] * INV_T;
            }
        }
    }
}

// ---------------------------------------------------------------------------
// Prototype logits + label zeroing.
// ---------------------------------------------------------------------------
__global__ void proto_kernel(const float* __restrict__ X,
                             const float* __restrict__ P,
                             const int* __restrict__ c2c,
                             float* __restrict__ lp,
                             float* __restrict__ labels,
                             float* __restrict__ labels_p)
{
    __shared__ float Ps[64][60];
    __shared__ float Xs[4][60];

    const int tid = threadIdx.x;
    const int row0 = blockIdx.x * 4;

    for (int e = tid; e < 64 * 60; e += 256) Ps[e / 60][e % 60] = P[e];
    for (int e = tid; e < 4 * 60; e += 256)
        Xs[e / 60][e % 60] = X[(row0 + e / 60) * 60 + e % 60];
    __syncthreads();

    const int r = tid >> 6;
    const int c = tid & 63;
    const int n = row0 + r;

    float acc = 0.0f;
#pragma unroll
    for (int i = 0; i < 60; i++) acc += Xs[r][i] * Ps[c][i];

    const int cc = c2c[n];
    int pos = (c == cc) ? 0 : ((c < cc) ? c + 1 : c);
    lp[(size_t)n * 64 + pos] = acc;

    if (c == 0) {
        labels[n]   = 0.0f;
        labels_p[n] = 0.0f;
    }
}

// ---------------------------------------------------------------------------
// Launcher
// ---------------------------------------------------------------------------
extern "C" void kernel_launch(void* const* d_in, const int* in_sizes, int n_in,
                              void* d_out, int out_size)
{
    const float* omics_q = (const float*)d_in[0];
    const float* omics_k = (const float*)d_in[1];
    const float* protos  = (const float*)d_in[2];
    const float* re_w1 = (const float*)d_in[3];
    const float* re_b1 = (const float*)d_in[4];
    const float* re_w2 = (const float*)d_in[5];
    const float* re_b2 = (const float*)d_in[6];
    const float* re_w3 = (const float*)d_in[7];
    const float* re_b3 = (const float*)d_in[8];
    const float* rd_w1 = (const float*)d_in[9];
    const float* rd_b1 = (const float*)d_in[10];
    const float* rd_w2 = (const float*)d_in[11];
    const float* rd_b2 = (const float*)d_in[12];
    const float* rd_w3 = (const float*)d_in[13];
    const float* rd_b3 = (const float*)d_in[14];
    const float* me_w1 = (const float*)d_in[15];
    const float* me_b1 = (const float*)d_in[16];
    const float* me_w2 = (const float*)d_in[17];
    const float* me_b2 = (const float*)d_in[18];
    const float* me_w3 = (const float*)d_in[19];
    const float* me_b3 = (const float*)d_in[20];
    const float* md_w1 = (const float*)d_in[21];
    const float* md_b1 = (const float*)d_in[22];
    const float* md_w2 = (const float*)d_in[23];
    const float* md_b2 = (const float*)d_in[24];
    const float* md_w3 = (const float*)d_in[25];
    const float* md_b3 = (const float*)d_in[26];
    const float* lr_w  = (const float*)d_in[27];
    const float* lr_b  = (const float*)d_in[28];
    const float* lm_w  = (const float*)d_in[29];
    const float* lm_b  = (const float*)d_in[30];
    const int*   c2c   = (const int*)d_in[31];

    float* scratch = nullptr;
    cudaGetSymbolAddress((void**)&scratch, g_scratch);

    float* out    = (float*)d_out;
    float* rna    = out;                              // 2048*20000
    float* mirna  = out + 40960000;                   // 2048*2000
    float* logits = out + 45056000;                   // 2048*4095
    float* labels = out + 53442560;                   // 2048
    float* lproto = out + 53444608;                   // 2048*64
    float* lplab  = out + 53575680;                   // 2048

    dim3 blk(256);

    // ---- encoders L1 (big-K GEMMs): split-K=8, 512 blocks each ----
    bgemm_splitk<<<dim3(4, 16, ZSPLIT), blk>>>(omics_q, re_w1, scratch + O_PQ,
                                               NROWS, 200, D_R, 2512);
    bgemm_splitk<<<dim3(4, 16, ZSPLIT), blk>>>(omics_k, me_w1, scratch + O_PK,
                                               NROWS, 200, D_M, 256);
    {
        RedJobs rj;
        rj.P[0] = scratch + O_PQ;  rj.bias[0] = re_b1;  rj.C[0] = scratch + O_Q1;
        rj.P[1] = scratch + O_PK;  rj.bias[1] = me_b1;  rj.C[1] = scratch + O_K1;
        reduce_splitk<<<dim3(400, 1, 2), blk>>>(rj, NROWS, 200);
    }

    // ---- encoders L2 (batched q/k) ----
    {
        GemmJobs j;
        j.A[0] = scratch + O_Q1; j.B[0] = re_w2; j.bias[0] = re_b2; j.C[0] = scratch + O_Q2; j.act[0] = 1;
        j.A[1] = scratch + O_K1; j.B[1] = me_w2; j.bias[1] = me_b2; j.C[1] = scratch + O_K2; j.act[1] = 1;
        sgemm_batch<<<dim3(1, 32, 2), blk>>>(j, NROWS, 50, 200);
    }
    // ---- encoders L3 (batched q/k) ----
    {
        GemmJobs j;
        j.A[0] = scratch + O_Q2; j.B[0] = re_w3; j.bias[0] = re_b3; j.C[0] = scratch + O_Q; j.act[0] = 0;
        j.A[1] = scratch + O_K2; j.B[1] = me_w3; j.bias[1] = me_b3; j.C[1] = scratch + O_K; j.act[1] = 0;
        sgemm_batch<<<dim3(1, 32, 2), blk>>>(j, NROWS, 50, 50);
    }
    // ---- decoder L1 (q,k) + bilinear tq,tk: 4 jobs, all 2048x50x50 ----
    {
        GemmJobs j;
        j.A[0] = scratch + O_Q; j.B[0] = rd_w1; j.bias[0] = rd_b1; j.C[0] = scratch + O_H1;  j.act[0] = 1;
        j.A[1] = scratch + O_K; j.B[1] = md_w1; j.bias[1] = md_b1; j.C[1] = scratch + O_HK1; j.act[1] = 1;
        j.A[2] = scratch + O_Q; j.B[2] = lr_w;  j.bias[2] = lr_b;  j.C[2] = scratch + O_TQ;  j.act[2] = 0;
        j.A[3] = scratch + O_K; j.B[3] = lm_w;  j.bias[3] = lm_b;  j.C[3] = scratch + O_TK;  j.act[3] = 0;
        sgemm_batch<<<dim3(1, 32, 4), blk>>>(j, NROWS, 50, 50);
    }
    // ---- decoder L2 (batched q/k) ----
    {
        GemmJobs j;
        j.A[0] = scratch + O_H1;  j.B[0] = rd_w2; j.bias[0] = rd_b2; j.C[0] = scratch + O_H2;  j.act[0] = 1;
        j.A[1] = scratch + O_HK1; j.B[1] = md_w2; j.bias[1] = md_b2; j.C[1] = scratch + O_HK2; j.act[1] = 1;
        sgemm_batch<<<dim3(4, 32, 2), blk>>>(j, NROWS, 200, 50);
    }

    // ---- decoder L3 (big-N GEMMs, sigmoid) ----
    bgemm_act<<<dim3(313, 16), blk>>>(scratch + O_H2,  rd_w3, rd_b3, rna,   NROWS, D_R, 200, 2);
    bgemm_act<<<dim3(32, 16),  blk>>>(scratch + O_HK2, md_w3, md_b3, mirna, NROWS, D_M, 200, 2);

    // ---- fused X ----
    fuse_X_kernel<<<16, 128>>>(scratch + O_Q, scratch + O_K,
                               scratch + O_TQ, scratch + O_TK, scratch + O_X);

    // ---- contrastive logits ----
    logits_kernel<<<dim3(32, 32), blk>>>(scratch + O_Q, scratch + O_K, logits);

    // ---- prototype logits + labels ----
    proto_kernel<<<512, blk>>>(scratch + O_X, protos, c2c, lproto, labels, lplab);
}